// round 6
// baseline (speedup 1.0000x reference)
#include <cuda_runtime.h>
#include <math.h>

#define GRID_S   14
#define NCELL    (GRID_S * GRID_S)   // 196
#define NCLS     20
#define MAXOBJ   20
#define THREADS  256
#define MAXBS    4096

// Per-CTA partial sums, [batch][8] so the final kernel reads 2 coalesced float4s.
// comps: 0 noobj, 1 objconf, 2 xy, 3 wh, 4 clc, 5 n_noobj, 6 n_resp, 7 n_obj
__device__ float g_part[MAXBS][8];

__inline__ __device__ float warpReduceF(float v) {
    #pragma unroll
    for (int o = 16; o > 0; o >>= 1) v += __shfl_down_sync(0xffffffffu, v, o);
    return v;
}
__inline__ __device__ double warpReduceD(double v) {
    #pragma unroll
    for (int o = 16; o > 0; o >>= 1) v += __shfl_down_sync(0xffffffffu, v, o);
    return v;
}

__global__ void __launch_bounds__(THREADS)
yolo_main_kernel(const float* __restrict__ pred,
                 const float* __restrict__ target) {
    __shared__ float    s_conf[2][NCELL][5];        // 7840 B
    __shared__ unsigned s_clsmask[NCELL];
    __shared__ float s_obj_f[MAXOBJ][4];            // offx, offy, w, h
    __shared__ int   s_obj_i[MAXOBJ][4];            // valid, mi, cell, cls
    __shared__ float s_redf[8][8];

    const int b   = blockIdx.x;
    const int tid = threadIdx.x;
    const float* __restrict__ pimg = pred + (long long)b * (NCELL * 30);

    // ---- Phase A: zero shared target state ----
    for (int i = tid; i < 2 * NCELL * 5; i += THREADS)
        ((float*)s_conf)[i] = 0.0f;
    for (int i = tid; i < NCELL; i += THREADS)
        s_clsmask[i] = 0u;

    // ---- Phase B1: per-object precompute (parallel; gathers 10 pred floats) ----
    if (tid < MAXOBJ) {
        const float* t = target + ((long long)b * MAXOBJ + tid) * 5;
        float x1 = t[0], y1 = t[1], x2 = t[2], y2 = t[3], cls = t[4];
        float s5 = x1 + y1 + x2 + y2 + cls;
        int valid = (s5 != 0.0f) ? 1 : 0;

        const float fg = (float)GRID_S;
        float cx = (x1 + x2) * 0.5f * fg;
        float cy = (y1 + y2) * 0.5f * fg;
        float w  = x2 - x1;
        float h  = y2 - y1;
        int gx = (int)floorf(cx); gx = min(max(gx, 0), GRID_S - 1);
        int gy = (int)floorf(cy); gy = min(max(gy, 0), GRID_S - 1);
        float offx = cx - (float)gx;
        float offy = cy - (float)gy;

        const float* pb = pimg + (gy * GRID_S + gx) * 30;
        float tcx = offx / fg, tcy = offy / fg;
        float t_ltx = tcx - 0.5f * w, t_lty = tcy - 0.5f * h;
        float t_rbx = tcx + 0.5f * w, t_rby = tcy + 0.5f * h;
        float a2 = (t_rbx - t_ltx) * (t_rby - t_lty);

        float iou[2];
        #pragma unroll
        for (int j = 0; j < 2; j++) {
            float px = pb[j * 5 + 1] / fg;
            float py = pb[j * 5 + 2] / fg;
            float pw = pb[j * 5 + 3];
            float ph = pb[j * 5 + 4];
            float p_ltx = px - 0.5f * pw, p_lty = py - 0.5f * ph;
            float p_rbx = px + 0.5f * pw, p_rby = py + 0.5f * ph;
            float ltx = fmaxf(p_ltx, t_ltx), lty = fmaxf(p_lty, t_lty);
            float rbx = fminf(p_rbx, t_rbx), rby = fminf(p_rby, t_rby);
            float wi = fmaxf(rbx - ltx, 0.0f);
            float hi = fmaxf(rby - lty, 0.0f);
            float inter = wi * hi;
            float a1 = (p_rbx - p_ltx) * (p_rby - p_lty);
            iou[j] = inter / (a1 + a2 - inter);
        }
        int mi = (iou[1] > iou[0]) ? 1 : 0;   // argmax: first index on ties

        s_obj_i[tid][0] = valid;
        s_obj_i[tid][1] = mi;
        s_obj_i[tid][2] = gy * GRID_S + gx;
        s_obj_i[tid][3] = (int)cls;
        s_obj_f[tid][0] = offx;
        s_obj_f[tid][1] = offy;
        s_obj_f[tid][2] = w;
        s_obj_f[tid][3] = h;
    }
    __syncthreads();

    // ---- Phase B2: sequential commit (preserves last-write-wins ordering) ----
    if (tid == 0) {
        #pragma unroll
        for (int o = 0; o < MAXOBJ; o++) {
            if (s_obj_i[o][0]) {
                int mi = s_obj_i[o][1];
                int cell = s_obj_i[o][2];
                s_conf[mi][cell][0] = 1.0f;
                s_conf[mi][cell][1] = s_obj_f[o][0];
                s_conf[mi][cell][2] = s_obj_f[o][1];
                s_conf[mi][cell][3] = s_obj_f[o][2];
                s_conf[mi][cell][4] = s_obj_f[o][3];
                s_clsmask[cell] |= (1u << s_obj_i[o][3]);
            }
        }
    }
    __syncthreads();

    // ---- Phase C: per-cell loss. Only conf sectors touched for noobj cells;
    //      coords/class channels loaded under the (rare) obj predicate. ----
    float l_noobj = 0.0f, l_objconf = 0.0f, l_xy = 0.0f, l_wh = 0.0f, l_clc = 0.0f;
    float c_noobj = 0.0f, c_resp = 0.0f, c_obj = 0.0f;

    for (int cell = tid; cell < NCELL; cell += THREADS) {
        const float* p = pimg + cell * 30;
        float pc0 = p[0];                 // box0 conf
        float pc1 = p[5];                 // box1 conf (same/adjacent sector)
        float c0 = s_conf[0][cell][0];
        float c1 = s_conf[1][cell][0];
        float csum = c0 + c1;             // exact: values in {0,1}
        bool obj   = (csum == 1.0f);
        bool noobj = (csum == 0.0f);

        if (noobj) {
            l_noobj += pc0 * pc0 + pc1 * pc1;
            c_noobj += 2.0f;
        }
        if (obj) {
            #pragma unroll
            for (int j = 0; j < 2; j++) {
                bool bset = ((j == 0 ? c0 : c1) == 1.0f);
                if (bset) {
                    float pc = (j == 0) ? pc0 : pc1;
                    c_resp += 1.0f;
                    float d = pc - 1.0f;
                    l_objconf += d * d;
                    float dx = p[j * 5 + 1] - s_conf[j][cell][1];
                    float dy = p[j * 5 + 2] - s_conf[j][cell][2];
                    l_xy += dx * dx + dy * dy;
                    float dw = sqrtf(p[j * 5 + 3]) - sqrtf(s_conf[j][cell][3]);
                    float dh = sqrtf(p[j * 5 + 4]) - sqrtf(s_conf[j][cell][4]);
                    l_wh += dw * dw + dh * dh;
                }
            }
            c_obj += 1.0f;
            unsigned mask = s_clsmask[cell];
            #pragma unroll
            for (int c = 0; c < NCLS; c++) {
                float t = ((mask >> c) & 1u) ? 1.0f : 0.0f;
                float d = p[10 + c] - t;
                l_clc += d * d;
            }
        }
    }

    // ---- Block reduction to 8 per-CTA partials (plain STG, no atomics) ----
    int wid = tid >> 5, lane = tid & 31;
    float vals[8] = { l_noobj, l_objconf, l_xy, l_wh, l_clc, c_noobj, c_resp, c_obj };
    #pragma unroll
    for (int c = 0; c < 8; c++) {
        vals[c] = warpReduceF(vals[c]);
        if (lane == 0) s_redf[c][wid] = vals[c];
    }
    __syncthreads();
    if (tid < 8) {
        float s = 0.0f;
        #pragma unroll
        for (int wv = 0; wv < THREADS / 32; wv++) s += s_redf[tid][wv];
        g_part[b][tid] = s;
    }
}

__global__ void __launch_bounds__(THREADS)
yolo_final_kernel(float* __restrict__ out, int bs) {
    // Each thread accumulates all 8 comps over strided batch rows (coalesced
    // float4 pairs, independent loads), then block-reduce in double.
    __shared__ double s_redd[8][8];
    const int tid = threadIdx.x;
    int wid = tid >> 5, lane = tid & 31;

    double acc[8] = {0, 0, 0, 0, 0, 0, 0, 0};
    for (int i = tid; i < bs; i += THREADS) {
        float4 a = *(const float4*)&g_part[i][0];
        float4 c = *(const float4*)&g_part[i][4];
        acc[0] += (double)a.x; acc[1] += (double)a.y;
        acc[2] += (double)a.z; acc[3] += (double)a.w;
        acc[4] += (double)c.x; acc[5] += (double)c.y;
        acc[6] += (double)c.z; acc[7] += (double)c.w;
    }
    #pragma unroll
    for (int c = 0; c < 8; c++) {
        acc[c] = warpReduceD(acc[c]);
        if (lane == 0) s_redd[c][wid] = acc[c];
    }
    __syncthreads();
    if (tid == 0) {
        double tot[8];
        #pragma unroll
        for (int c = 0; c < 8; c++) {
            double s = 0.0;
            #pragma unroll
            for (int wv = 0; wv < THREADS / 32; wv++) s += s_redd[c][wv];
            tot[c] = s;
        }
        double n_noobj = tot[5], n_resp = tot[6], n_obj = tot[7];
        double loss_xy      = tot[2] / (n_resp * 2.0);
        double loss_wh      = tot[3] / (n_resp * 2.0);
        double objconf_loss = tot[1] / n_resp;
        double noobj_loss   = tot[0] / n_noobj;
        double loss_clc     = tot[4] / (n_obj * (double)NCLS);
        out[0] = (float)(5.0 * (loss_xy + loss_wh) + objconf_loss +
                         0.5 * noobj_loss + loss_clc);
    }
}

extern "C" void kernel_launch(void* const* d_in, const int* in_sizes, int n_in,
                              void* d_out, int out_size) {
    const float* pred   = (const float*)d_in[0];
    const float* target = (const float*)d_in[1];
    int bs = in_sizes[1] / (MAXOBJ * 5);

    yolo_main_kernel<<<bs, THREADS>>>(pred, target);
    yolo_final_kernel<<<1, THREADS>>>((float*)d_out, bs);
}

// round 9
// speedup vs baseline: 1.4735x; 1.4735x over previous
#include <cuda_runtime.h>
#include <math.h>

#define GRID_S   14
#define NCELL    (GRID_S * GRID_S)   // 196
#define NCLS     20
#define MAXOBJ   20
#define THREADS  256
#define IMGS     2                   // images per CTA
#define MAXPART  2048

// Per-CTA partial sums, [cta][8]; final kernel reads 2 coalesced float4s per row.
// comps: 0 noobj, 1 objconf, 2 xy, 3 wh, 4 clc, 5 n_noobj, 6 n_resp, 7 n_obj
__device__ float g_part[MAXPART][8];

__inline__ __device__ float warpReduceF(float v) {
    #pragma unroll
    for (int o = 16; o > 0; o >>= 1) v += __shfl_down_sync(0xffffffffu, v, o);
    return v;
}

__global__ void __launch_bounds__(THREADS)
yolo_main_kernel(const float* __restrict__ pred,
                 const float* __restrict__ target) {
    __shared__ float    s_conf[IMGS][2][NCELL][5];
    __shared__ unsigned s_clsmask[IMGS][NCELL];
    __shared__ float s_obj_f[IMGS][MAXOBJ][4];      // offx, offy, w, h
    __shared__ int   s_obj_i[IMGS][MAXOBJ][4];      // valid, mi, cell, cls
    __shared__ float s_redf[8][8];

    const int b0  = blockIdx.x * IMGS;
    const int tid = threadIdx.x;

    // ---- Phase A: zero shared target state ----
    for (int i = tid; i < IMGS * 2 * NCELL * 5; i += THREADS)
        ((float*)s_conf)[i] = 0.0f;
    for (int i = tid; i < IMGS * NCELL; i += THREADS)
        ((unsigned*)s_clsmask)[i] = 0u;

    // ---- Phase B1: per-object precompute, parallel across IMGS*MAXOBJ ----
    if (tid < IMGS * MAXOBJ) {
        const int img = tid / MAXOBJ;
        const int o   = tid % MAXOBJ;
        const float* pimg = pred + (long long)(b0 + img) * (NCELL * 30);
        const float* t = target + ((long long)(b0 + img) * MAXOBJ + o) * 5;
        float x1 = t[0], y1 = t[1], x2 = t[2], y2 = t[3], cls = t[4];
        float s5 = x1 + y1 + x2 + y2 + cls;
        int valid = (s5 != 0.0f) ? 1 : 0;

        const float fg = (float)GRID_S;
        float cx = (x1 + x2) * 0.5f * fg;
        float cy = (y1 + y2) * 0.5f * fg;
        float w  = x2 - x1;
        float h  = y2 - y1;
        int gx = (int)floorf(cx); gx = min(max(gx, 0), GRID_S - 1);
        int gy = (int)floorf(cy); gy = min(max(gy, 0), GRID_S - 1);
        float offx = cx - (float)gx;
        float offy = cy - (float)gy;

        const float* pb = pimg + (gy * GRID_S + gx) * 30;
        float tcx = offx / fg, tcy = offy / fg;
        float t_ltx = tcx - 0.5f * w, t_lty = tcy - 0.5f * h;
        float t_rbx = tcx + 0.5f * w, t_rby = tcy + 0.5f * h;
        float a2 = (t_rbx - t_ltx) * (t_rby - t_lty);

        float iou[2];
        #pragma unroll
        for (int j = 0; j < 2; j++) {
            float px = pb[j * 5 + 1] / fg;
            float py = pb[j * 5 + 2] / fg;
            float pw = pb[j * 5 + 3];
            float ph = pb[j * 5 + 4];
            float p_ltx = px - 0.5f * pw, p_lty = py - 0.5f * ph;
            float p_rbx = px + 0.5f * pw, p_rby = py + 0.5f * ph;
            float ltx = fmaxf(p_ltx, t_ltx), lty = fmaxf(p_lty, t_lty);
            float rbx = fminf(p_rbx, t_rbx), rby = fminf(p_rby, t_rby);
            float wi = fmaxf(rbx - ltx, 0.0f);
            float hi = fmaxf(rby - lty, 0.0f);
            float inter = wi * hi;
            float a1 = (p_rbx - p_ltx) * (p_rby - p_lty);
            iou[j] = inter / (a1 + a2 - inter);
        }
        int mi = (iou[1] > iou[0]) ? 1 : 0;   // argmax: first index on ties

        s_obj_i[img][o][0] = valid;
        s_obj_i[img][o][1] = mi;
        s_obj_i[img][o][2] = gy * GRID_S + gx;
        s_obj_i[img][o][3] = (int)cls;
        s_obj_f[img][o][0] = offx;
        s_obj_f[img][o][1] = offy;
        s_obj_f[img][o][2] = w;
        s_obj_f[img][o][3] = h;
    }
    __syncthreads();

    // ---- Phase B2: sequential commit per image (IMGS commits in parallel) ----
    if (tid < IMGS) {
        const int img = tid;
        #pragma unroll
        for (int o = 0; o < MAXOBJ; o++) {
            if (s_obj_i[img][o][0]) {
                int mi = s_obj_i[img][o][1];
                int cell = s_obj_i[img][o][2];
                s_conf[img][mi][cell][0] = 1.0f;
                s_conf[img][mi][cell][1] = s_obj_f[img][o][0];
                s_conf[img][mi][cell][2] = s_obj_f[img][o][1];
                s_conf[img][mi][cell][3] = s_obj_f[img][o][2];
                s_conf[img][mi][cell][4] = s_obj_f[img][o][3];
                s_clsmask[img][cell] |= (1u << s_obj_i[img][o][3]);
            }
        }
    }
    __syncthreads();

    // ---- Phase C: per-cell loss over IMGS images ----
    float l_noobj = 0.0f, l_objconf = 0.0f, l_xy = 0.0f, l_wh = 0.0f, l_clc = 0.0f;
    float c_noobj = 0.0f, c_resp = 0.0f, c_obj = 0.0f;

    for (int idx = tid; idx < IMGS * NCELL; idx += THREADS) {
        const int img  = idx / NCELL;
        const int cell = idx % NCELL;
        const float* p = pred + (long long)(b0 + img) * (NCELL * 30) + cell * 30;
        float pc0 = p[0];                 // box0 conf
        float pc1 = p[5];                 // box1 conf
        float c0 = s_conf[img][0][cell][0];
        float c1 = s_conf[img][1][cell][0];
        float csum = c0 + c1;             // exact: values in {0,1}
        bool obj   = (csum == 1.0f);
        bool noobj = (csum == 0.0f);

        if (noobj) {
            l_noobj += pc0 * pc0 + pc1 * pc1;
            c_noobj += 2.0f;
        }
        if (obj) {
            #pragma unroll
            for (int j = 0; j < 2; j++) {
                bool bset = ((j == 0 ? c0 : c1) == 1.0f);
                if (bset) {
                    float pc = (j == 0) ? pc0 : pc1;
                    c_resp += 1.0f;
                    float d = pc - 1.0f;
                    l_objconf += d * d;
                    float dx = p[j * 5 + 1] - s_conf[img][j][cell][1];
                    float dy = p[j * 5 + 2] - s_conf[img][j][cell][2];
                    l_xy += dx * dx + dy * dy;
                    float dw = sqrtf(p[j * 5 + 3]) - sqrtf(s_conf[img][j][cell][3]);
                    float dh = sqrtf(p[j * 5 + 4]) - sqrtf(s_conf[img][j][cell][4]);
                    l_wh += dw * dw + dh * dh;
                }
            }
            c_obj += 1.0f;
            unsigned mask = s_clsmask[img][cell];
            #pragma unroll
            for (int c = 0; c < NCLS; c++) {
                float t = ((mask >> c) & 1u) ? 1.0f : 0.0f;
                float d = p[10 + c] - t;
                l_clc += d * d;
            }
        }
    }

    // ---- Block reduction to 8 per-CTA partials ----
    int wid = tid >> 5, lane = tid & 31;
    float vals[8] = { l_noobj, l_objconf, l_xy, l_wh, l_clc, c_noobj, c_resp, c_obj };
    #pragma unroll
    for (int c = 0; c < 8; c++) {
        vals[c] = warpReduceF(vals[c]);
        if (lane == 0) s_redf[c][wid] = vals[c];
    }
    __syncthreads();
    if (tid < 8) {
        float s = 0.0f;
        #pragma unroll
        for (int wv = 0; wv < THREADS / 32; wv++) s += s_redf[tid][wv];
        g_part[blockIdx.x][tid] = s;
    }
}

__global__ void __launch_bounds__(THREADS)
yolo_final_kernel(float* __restrict__ out, int nparts) {
    // fp32 accumulation (no fp64 in the hot loop — FP64 pipe is ~1/18 rate/SM).
    __shared__ float s_redf[8][8];
    const int tid = threadIdx.x;
    int wid = tid >> 5, lane = tid & 31;

    float acc[8] = {0, 0, 0, 0, 0, 0, 0, 0};
    for (int i = tid; i < nparts; i += THREADS) {
        float4 a = *(const float4*)&g_part[i][0];
        float4 c = *(const float4*)&g_part[i][4];
        acc[0] += a.x; acc[1] += a.y; acc[2] += a.z; acc[3] += a.w;
        acc[4] += c.x; acc[5] += c.y; acc[6] += c.z; acc[7] += c.w;
    }
    #pragma unroll
    for (int c = 0; c < 8; c++) {
        acc[c] = warpReduceF(acc[c]);
        if (lane == 0) s_redf[c][wid] = acc[c];
    }
    __syncthreads();
    if (tid == 0) {
        double tot[8];
        #pragma unroll
        for (int c = 0; c < 8; c++) {
            float s = 0.0f;
            #pragma unroll
            for (int wv = 0; wv < THREADS / 32; wv++) s += s_redf[c][wv];
            tot[c] = (double)s;
        }
        double n_noobj = tot[5], n_resp = tot[6], n_obj = tot[7];
        double loss_xy      = tot[2] / (n_resp * 2.0);
        double loss_wh      = tot[3] / (n_resp * 2.0);
        double objconf_loss = tot[1] / n_resp;
        double noobj_loss   = tot[0] / n_noobj;
        double loss_clc     = tot[4] / (n_obj * (double)NCLS);
        out[0] = (float)(5.0 * (loss_xy + loss_wh) + objconf_loss +
                         0.5 * noobj_loss + loss_clc);
    }
}

extern "C" void kernel_launch(void* const* d_in, const int* in_sizes, int n_in,
                              void* d_out, int out_size) {
    const float* pred   = (const float*)d_in[0];
    const float* target = (const float*)d_in[1];
    int bs = in_sizes[1] / (MAXOBJ * 5);
    int nctas = bs / IMGS;

    yolo_main_kernel<<<nctas, THREADS>>>(pred, target);
    yolo_final_kernel<<<1, THREADS>>>((float*)d_out, nctas);
}